// round 16
// baseline (speedup 1.0000x reference)
#include <cuda_runtime.h>
#include <cuda_fp16.h>
#include <math.h>
#include <stdint.h>

#define B_ 2
#define N_ 4096
#define D_ 512
#define H_ 8
#define HD_ 64
#define QKVD (3*D_)
#define BN (B_*N_)

// Scratch (device globals; no allocations allowed)
__device__ __half g_xh  [BN*D_];      // x + PE, fp16
__device__ __half g_wqkv[D_*QKVD];    // qkv_w fp16
__device__ __half g_wlin[D_*D_];      // lin_w fp16
__device__ __half g_qkvh[BN*QKVD];    // qkv projection fp16
__device__ __half g_aoh [BN*D_];      // attention output fp16

// ---------------------------------------------------------------------------
// helpers (arch-agnostic PTX: ldmatrix / mma.sync / cp.async, sm_80+)
// ---------------------------------------------------------------------------
__device__ __forceinline__ uint32_t smem_u32(const void* p) {
    uint32_t a;
    asm("{ .reg .u64 t; cvta.to.shared.u64 t, %1; cvt.u32.u64 %0, t; }" : "=r"(a) : "l"(p));
    return a;
}
__device__ __forceinline__ void ldsm4(uint32_t* r, uint32_t a) {
    asm volatile("ldmatrix.sync.aligned.m8n8.x4.shared.b16 {%0,%1,%2,%3}, [%4];"
        : "=r"(r[0]), "=r"(r[1]), "=r"(r[2]), "=r"(r[3]) : "r"(a));
}
__device__ __forceinline__ void ldsm4t(uint32_t* r, uint32_t a) {
    asm volatile("ldmatrix.sync.aligned.m8n8.x4.trans.shared.b16 {%0,%1,%2,%3}, [%4];"
        : "=r"(r[0]), "=r"(r[1]), "=r"(r[2]), "=r"(r[3]) : "r"(a));
}
__device__ __forceinline__ void mma16816(float* d, const uint32_t* a, const uint32_t* b) {
    asm volatile("mma.sync.aligned.m16n8k16.row.col.f32.f16.f16.f32 "
        "{%0,%1,%2,%3}, {%4,%5,%6,%7}, {%8,%9}, {%0,%1,%2,%3};"
        : "+f"(d[0]), "+f"(d[1]), "+f"(d[2]), "+f"(d[3])
        : "r"(a[0]), "r"(a[1]), "r"(a[2]), "r"(a[3]), "r"(b[0]), "r"(b[1]));
}
// pack two fp32 -> f16x2 (lo = zlo), then 2^x elementwise
__device__ __forceinline__ uint32_t exp2h2(float zhi, float zlo) {
    uint32_t u;
    asm("cvt.rn.f16x2.f32 %0, %1, %2;" : "=r"(u) : "f"(zhi), "f"(zlo));
    asm("ex2.approx.f16x2 %0, %0;" : "+r"(u));
    return u;
}
#define CP16(sa, ga) \
    asm volatile("cp.async.cg.shared.global [%0], [%1], 16;" :: "r"(sa), "l"(ga))
#define CP_COMMIT() asm volatile("cp.async.commit_group;" ::: "memory")
#define CP_WAIT1()  asm volatile("cp.async.wait_group 1;" ::: "memory")
#define CP_WAIT0()  asm volatile("cp.async.wait_group 0;" ::: "memory")

// ---------------------------------------------------------------------------
// Merged elementwise kernel (R13, proven): PE-add + weight conversion.
// ---------------------------------------------------------------------------
#define PE_PAIRS  (BN*D_/2)
#define PE_BLOCKS (PE_PAIRS/256)
#define QKV_F4 (D_*QKVD/4)
#define LIN_F4 (D_*D_/4)
#define EW_BLOCKS (PE_BLOCKS + (QKV_F4 + LIN_F4)/256)

__global__ void elementwise_kernel(const float* __restrict__ x,
                                   const float* __restrict__ qkv_w,
                                   const float* __restrict__ lin_w) {
    if (blockIdx.x < PE_BLOCKS) {
        int i = blockIdx.x * blockDim.x + threadIdx.x;   // pair index
        int dp = i & (D_/2 - 1);
        int n = (i >> 8) & (N_ - 1);
        float inv = exp2f((float)dp * -0.051905126482615044f); // log2(1e4)/256
        float angle = (float)n * inv;
        float s, c;
        sincosf(angle, &s, &c);
        float2 xv = ((const float2*)x)[i];
        __half2 hv = __floats2half2_rn(xv.x + s, xv.y + c);
        ((__half2*)g_xh)[i] = hv;
    } else {
        int i = (blockIdx.x - PE_BLOCKS) * blockDim.x + threadIdx.x;
        const float* src;
        __half* dst;
        int j;
        if (i < QKV_F4) { src = qkv_w; dst = g_wqkv; j = i; }
        else            { src = lin_w; dst = g_wlin; j = i - QKV_F4; }
        float4 v = ((const float4*)src)[j];
        __half2 a = __floats2half2_rn(v.x, v.y);
        __half2 b = __floats2half2_rn(v.z, v.w);
        ((uint2*)dst)[j] = make_uint2(*(uint32_t*)&a, *(uint32_t*)&b);
    }
}

// ---------------------------------------------------------------------------
// HGEMM with cp.async double buffering. Block 128x128, 8 warps, k-step 32.
// (proven R4/R6/R13 configuration — untouched)
// ---------------------------------------------------------------------------
#define SA_ST 5120   // halves per A stage (128*40)
#define SB_ST 4352   // halves per B stage (32*136)

__device__ __forceinline__ void hg_issue(
    uint32_t sAa, uint32_t sBa, int stage,
    const __half* __restrict__ A, const __half* __restrict__ Bw,
    int m0, int n0, int k0, int N, int K, int tid)
{
    const int ar = tid >> 2, ac = (tid & 3) * 8;
    const int br = tid >> 4, bc = (tid & 15) * 8;
    uint32_t sa = sAa + (uint32_t)stage * SA_ST * 2;
    uint32_t sb = sBa + (uint32_t)stage * SB_ST * 2;
    CP16(sa + (ar*40 + ac)*2,       A + (size_t)(m0+ar)*K + k0 + ac);
    CP16(sa + ((ar+64)*40 + ac)*2,  A + (size_t)(m0+ar+64)*K + k0 + ac);
    CP16(sb + (br*136 + bc)*2,      Bw + (size_t)(k0+br)*N + n0 + bc);
    CP16(sb + ((br+16)*136 + bc)*2, Bw + (size_t)(k0+br+16)*N + n0 + bc);
}

template<int OUT_MODE>
__global__ __launch_bounds__(256) void hgemm_kernel(
    const __half* __restrict__ A, const __half* __restrict__ Bw,
    const float* __restrict__ bias, void* __restrict__ Cout,
    int M, int N, int K)
{
    __shared__ __half sA[2*SA_ST];
    __shared__ __half sB[2*SB_ST];

    const int tid = threadIdx.x;
    const int lane = tid & 31, warp = tid >> 5;
    const int wm = warp >> 2, wn = warp & 3;
    const int m0 = blockIdx.y * 128, n0 = blockIdx.x * 128;
    const int lq = lane >> 3;

    float acc[4][4][4];
    #pragma unroll
    for (int i = 0; i < 4; i++)
        #pragma unroll
        for (int j = 0; j < 4; j++)
            #pragma unroll
            for (int v = 0; v < 4; v++) acc[i][j][v] = 0.f;

    const uint32_t sAa = smem_u32(sA), sBa = smem_u32(sB);
    const int NK = K / 32;

    hg_issue(sAa, sBa, 0, A, Bw, m0, n0, 0, N, K, tid);  CP_COMMIT();
    hg_issue(sAa, sBa, 1, A, Bw, m0, n0, 32, N, K, tid); CP_COMMIT();

    for (int i = 0; i < NK; i++) {
        if (i == NK - 1) { CP_WAIT0(); } else { CP_WAIT1(); }
        __syncthreads();
        const uint32_t sa = sAa + (uint32_t)(i & 1) * SA_ST * 2;
        const uint32_t sb = sBa + (uint32_t)(i & 1) * SB_ST * 2;
        #pragma unroll
        for (int ks = 0; ks < 2; ks++) {
            uint32_t af[4][4];
            #pragma unroll
            for (int r = 0; r < 4; r++) {
                uint32_t addr = sa + (uint32_t)(((wm*64 + 16*r + (lane & 15))*40
                                  + ks*16 + (lane >> 4)*8) * 2);
                ldsm4(af[r], addr);
            }
            #pragma unroll
            for (int np = 0; np < 2; np++) {
                uint32_t bf[4];
                uint32_t addr = sb + (uint32_t)(((ks*16 + (lq & 1)*8 + (lane & 7))*136
                                  + wn*32 + np*16 + (lq >> 1)*8) * 2);
                ldsm4t(bf, addr);
                #pragma unroll
                for (int r = 0; r < 4; r++) {
                    mma16816(acc[r][2*np],   af[r], bf);
                    mma16816(acc[r][2*np+1], af[r], bf + 2);
                }
            }
        }
        __syncthreads();
        if (i + 2 < NK) {
            hg_issue(sAa, sBa, i & 1, A, Bw, m0, n0, (i+2)*32, N, K, tid);
            CP_COMMIT();
        }
    }

    const int g = lane >> 2, t = lane & 3;
    #pragma unroll
    for (int i = 0; i < 4; i++) {
        int r0 = m0 + wm*64 + 16*i + g;
        #pragma unroll
        for (int j = 0; j < 4; j++) {
            int col = n0 + wn*32 + 8*j + 2*t;
            if (OUT_MODE == 0) {
                __half* C = (__half*)Cout;
                __half2 h0 = __floats2half2_rn(acc[i][j][0], acc[i][j][1]);
                __half2 h1 = __floats2half2_rn(acc[i][j][2], acc[i][j][3]);
                *(__half2*)&C[(size_t)r0*N + col]     = h0;
                *(__half2*)&C[(size_t)(r0+8)*N + col] = h1;
            } else {
                float* C = (float*)Cout;
                float b0 = bias[col], b1 = bias[col+1];
                *(float2*)&C[(size_t)r0*N + col]     = make_float2(acc[i][j][0]+b0, acc[i][j][1]+b1);
                *(float2*)&C[(size_t)(r0+8)*N + col] = make_float2(acc[i][j][2]+b0, acc[i][j][3]+b1);
            }
        }
    }
}

// ---------------------------------------------------------------------------
// FA2 attention, 3-stage ring + SLICE-ROTATED softmax pipeline.
// Per jp-slice st: softmax(slice st) -> QK_next(slice st, reuses s regs) ->
// PV(slice st). Softmax slices are independent of in-flight QK/PV MMAs, so
// the tensor pipe never drains during softmax (the R13 s-register
// serialization is gone). Phase B feeds QK(kt+1, hf0) from ring stage kt+1,
// extending the rotation across the kt boundary. Numerics identical to R13.
// smem: 3 stages x (K[128][72] + V[128][72]) = 110.6 KB -> occupancy 2.
// ---------------------------------------------------------------------------
#define STG_B  36864u          // bytes per stage (K + V)
#define KV_B   18432u          // bytes per K (or V) tile
#define QOFF_H (2*18432)       // Q staging area: stage2 K-area, half index
#define ATTN_SMEM (3*36864)

__device__ __forceinline__ void issue_kv(uint32_t sma, int stage, int kt,
                                         int b, int h, int tid) {
    const __half* gk = g_qkvh + (size_t)(b*N_ + kt*128)*QKVD + h*HD_ + D_;
    uint32_t kb = sma + (uint32_t)stage * STG_B;
    uint32_t vb = kb + KV_B;
    #pragma unroll
    for (int it = 0; it < 8; it++) {
        int idx = tid + it*128;
        int r = idx >> 3, c = (idx & 7)*8;
        const __half* gp = gk + (size_t)r*QKVD + c;
        uint32_t so = (uint32_t)(r*72 + c)*2;
        CP16(kb + so, gp);
        CP16(vb + so, gp + D_);
    }
}

// QK slice jp=st (16 keys at key0+st*16), both mt, into s[*][2st..2st+1].
__device__ __forceinline__ void qk_slice(
    const uint32_t qf[2][4][4], uint32_t kb, int key0, int st, int lq, int lane,
    float s[2][8][4])
{
    #pragma unroll
    for (int mt = 0; mt < 2; mt++)
        #pragma unroll
        for (int v = 0; v < 4; v++) {
            s[mt][2*st][v] = 0.f;
            s[mt][2*st+1][v] = 0.f;
        }
    #pragma unroll
    for (int ds = 0; ds < 4; ds++) {
        uint32_t bf[4];
        uint32_t addr = kb + (uint32_t)((
              (key0 + st*16 + (lq >> 1)*8 + (lane & 7))*72
            + ds*16 + (lq & 1)*8) * 2);
        ldsm4(bf, addr);
        #pragma unroll
        for (int mt = 0; mt < 2; mt++) {
            mma16816(s[mt][2*st],   qf[mt][ds], bf);
            mma16816(s[mt][2*st+1], qf[mt][ds], bf + 2);
        }
    }
}

// softmax slice (one mt, jp=st): s rows 2st, 2st+1 -> 4 packed f16x2 regs.
__device__ __forceinline__ void softmax_slice_mt(
    const float sj0[4], const float sj1[4], uint32_t pf[4])
{
    const float EA = 0.125f * 1.4426950408889634f;
    const float EB = -8.f   * 1.4426950408889634f;
    pf[0] = exp2h2(fmaf(sj0[1], EA, EB), fmaf(sj0[0], EA, EB));
    pf[1] = exp2h2(fmaf(sj0[3], EA, EB), fmaf(sj0[2], EA, EB));
    pf[2] = exp2h2(fmaf(sj1[1], EA, EB), fmaf(sj1[0], EA, EB));
    pf[3] = exp2h2(fmaf(sj1[3], EA, EB), fmaf(sj1[2], EA, EB));
}

// PV slice jp=st: V fragment shared across mt.
__device__ __forceinline__ void pv_slice(
    const uint32_t p0[4], const uint32_t p1[4], uint32_t vb, int key0, int st,
    int lq, int lane, float o[2][8][4])
{
    #pragma unroll
    for (int nn = 0; nn < 4; nn++) {
        uint32_t vf[4];
        uint32_t addr = vb + (uint32_t)((
              (key0 + st*16 + (lq & 1)*8 + (lane & 7))*72
            + nn*16 + (lq >> 1)*8) * 2);
        ldsm4t(vf, addr);
        mma16816(o[0][2*nn],   p0, vf);
        mma16816(o[0][2*nn+1], p0, vf + 2);
        mma16816(o[1][2*nn],   p1, vf);
        mma16816(o[1][2*nn+1], p1, vf + 2);
    }
}

__global__ __launch_bounds__(128, 2) void attn_kernel() {
    extern __shared__ __half sm[];
    const uint32_t sma = smem_u32(sm);
    const int tid = threadIdx.x, lane = tid & 31, warp = tid >> 5;
    const int b = blockIdx.y >> 3, h = blockIdx.y & 7;
    const int q0 = blockIdx.x * 128;
    const int lq = lane >> 3;

    // prefetch K/V for kt=0,1 into stages 0,1 (don't touch stage 2 yet)
    issue_kv(sma, 0, 0, b, h, tid); CP_COMMIT();
    issue_kv(sma, 1, 1, b, h, tid); CP_COMMIT();

    // Q tile staged through stage-2's K-area
    #pragma unroll
    for (int it = 0; it < 8; it++) {
        int idx = tid + it * 128;
        int r = idx >> 3, c = (idx & 7) * 8;
        *(uint4*)&sm[QOFF_H + r*72 + c] =
            *(const uint4*)&g_qkvh[(size_t)(b*N_ + q0 + r)*QKVD + h*HD_ + c];
    }
    CP_WAIT1();        // g0 landed (issuing-thread); barrier below publishes
    __syncthreads();

    // Q fragments: warp rows [warp*32, warp*32+32), mt halves
    uint32_t qf[2][4][4];
    #pragma unroll
    for (int mt = 0; mt < 2; mt++)
        #pragma unroll
        for (int ds = 0; ds < 4; ds++) {
            uint32_t addr = sma + (uint32_t)((QOFF_H
                              + (warp*32 + mt*16 + (lane & 15))*72
                              + ds*16 + (lane >> 4)*8) * 2);
            ldsm4(qf[mt][ds], addr);
        }

    float o[2][8][4];
    #pragma unroll
    for (int mt = 0; mt < 2; mt++)
        #pragma unroll
        for (int j = 0; j < 8; j++)
            #pragma unroll
            for (int v = 0; v < 4; v++) o[mt][j][v] = 0.f;
    float lm[2][4] = {{0.f,0.f,0.f,0.f},{0.f,0.f,0.f,0.f}};
    uint32_t onesb[2] = {0x3C003C00u, 0x3C003C00u};  // f16 1.0 x4

    // prologue: S(kt=0, hf0) into s
    float s[2][8][4];
    #pragma unroll
    for (int st = 0; st < 4; st++)
        qk_slice(qf, sma, 0, st, lq, lane, s);

    int cur = 0;   // stage holding kt's K/V
    for (int kt = 0; kt < 32; kt++) {
        // all reads of stage (kt-1)%3 finished inside iteration kt-1
        __syncthreads();
        if (kt + 2 < 32) {
            int pre = cur + 2; if (pre >= 3) pre -= 3;
            issue_kv(sma, pre, kt + 2, b, h, tid);
            CP_COMMIT();
        }
        const uint32_t kb = sma + (uint32_t)cur * STG_B;
        const uint32_t vb = kb + KV_B;
        int nxt = cur + 1; if (nxt >= 3) nxt -= 3;
        const uint32_t kbn = sma + (uint32_t)nxt * STG_B;

        // phase A: softmax(hf0) slices rotated with QK(hf1) + PV(hf0)
        #pragma unroll
        for (int st = 0; st < 4; st++) {
            uint32_t p0[4], p1[4];
            softmax_slice_mt(s[0][2*st], s[0][2*st+1], p0);
            softmax_slice_mt(s[1][2*st], s[1][2*st+1], p1);
            mma16816(lm[0], p0, onesb);
            mma16816(lm[1], p1, onesb);
            qk_slice(qf, kb, 64, st, lq, lane, s);     // S(kt, hf1)
            pv_slice(p0, p1, vb, 0, st, lq, lane, o);  // O += P(hf0) @ V
        }

        // ensure g_{kt+1} landed before cross-kt QK reads stage nxt
        if (kt == 30)      { CP_WAIT0(); }
        else if (kt < 30)  { CP_WAIT1(); }

        // phase B: softmax(hf1) slices rotated with QK(kt+1, hf0) + PV(hf1)
        const bool do_next = (kt < 31);
        #pragma unroll
        for (int st = 0; st < 4; st++) {
            uint32_t p0[4], p1[4];
            softmax_slice_mt(s[0][2*st], s[0][2*st+1], p0);
            softmax_slice_mt(s[1][2*st], s[1][2*st+1], p1);
            mma16816(lm[0], p0, onesb);
            mma16816(lm[1], p1, onesb);
            if (do_next)
                qk_slice(qf, kbn, 0, st, lq, lane, s); // S(kt+1, hf0)
            pv_slice(p0, p1, vb, 64, st, lq, lane, o); // O += P(hf1) @ V
        }

        cur = nxt;
    }

    const int g = lane >> 2, t = lane & 3;
    #pragma unroll
    for (int mt = 0; mt < 2; mt++) {
        float inv0 = 1.f / lm[mt][0], inv1 = 1.f / lm[mt][2];
        const int r0 = q0 + warp*32 + mt*16 + g;
        #pragma unroll
        for (int j = 0; j < 8; j++) {
            int col = h*HD_ + 8*j + 2*t;
            __half2 h0 = __floats2half2_rn(o[mt][j][0]*inv0, o[mt][j][1]*inv0);
            __half2 h1 = __floats2half2_rn(o[mt][j][2]*inv1, o[mt][j][3]*inv1);
            *(__half2*)&g_aoh[(size_t)(b*N_ + r0)*D_ + col]     = h0;
            *(__half2*)&g_aoh[(size_t)(b*N_ + r0 + 8)*D_ + col] = h1;
        }
    }
}

// ---------------------------------------------------------------------------
extern "C" void kernel_launch(void* const* d_in, const int* in_sizes, int n_in,
                              void* d_out, int out_size) {
    const float* x     = (const float*)d_in[0];
    const float* qkv_w = (const float*)d_in[1];
    const float* lin_w = (const float*)d_in[2];
    const float* lin_b = (const float*)d_in[3];
    float* out = (float*)d_out;

    __half *xh, *wqkv, *wlin, *qkvh, *aoh;
    cudaGetSymbolAddress((void**)&xh,   g_xh);
    cudaGetSymbolAddress((void**)&wqkv, g_wqkv);
    cudaGetSymbolAddress((void**)&wlin, g_wlin);
    cudaGetSymbolAddress((void**)&qkvh, g_qkvh);
    cudaGetSymbolAddress((void**)&aoh,  g_aoh);

    cudaFuncSetAttribute(attn_kernel,
                         cudaFuncAttributeMaxDynamicSharedMemorySize, ATTN_SMEM);

    elementwise_kernel<<<EW_BLOCKS, 256>>>(x, qkv_w, lin_w);

    hgemm_kernel<0><<<dim3(QKVD/128, BN/128), 256>>>(
        xh, wqkv, nullptr, qkvh, BN, QKVD, D_);

    attn_kernel<<<dim3(N_/128, B_*H_), 128, ATTN_SMEM>>>();

    hgemm_kernel<1><<<dim3(D_/128, BN/128), 256>>>(
        aoh, wlin, lin_b, out, BN, D_, D_);
}

// round 17
// speedup vs baseline: 1.0886x; 1.0886x over previous
#include <cuda_runtime.h>
#include <cuda_fp16.h>
#include <math.h>
#include <stdint.h>

#define B_ 2
#define N_ 4096
#define D_ 512
#define H_ 8
#define HD_ 64
#define QKVD (3*D_)
#define BN (B_*N_)

// Scratch (device globals; no allocations allowed)
__device__ __half g_xh  [BN*D_];      // x + PE, fp16
__device__ __half g_wqkv[D_*QKVD];    // qkv_w fp16
__device__ __half g_wlin[D_*D_];      // lin_w fp16
__device__ __half g_qkvh[BN*QKVD];    // qkv projection fp16
__device__ __half g_aoh [BN*D_];      // attention output fp16

// ---------------------------------------------------------------------------
// helpers (arch-agnostic PTX: ldmatrix / mma.sync / cp.async, sm_80+)
// ---------------------------------------------------------------------------
__device__ __forceinline__ uint32_t smem_u32(const void* p) {
    uint32_t a;
    asm("{ .reg .u64 t; cvta.to.shared.u64 t, %1; cvt.u32.u64 %0, t; }" : "=r"(a) : "l"(p));
    return a;
}
__device__ __forceinline__ void ldsm4(uint32_t* r, uint32_t a) {
    asm volatile("ldmatrix.sync.aligned.m8n8.x4.shared.b16 {%0,%1,%2,%3}, [%4];"
        : "=r"(r[0]), "=r"(r[1]), "=r"(r[2]), "=r"(r[3]) : "r"(a));
}
__device__ __forceinline__ void ldsm4t(uint32_t* r, uint32_t a) {
    asm volatile("ldmatrix.sync.aligned.m8n8.x4.trans.shared.b16 {%0,%1,%2,%3}, [%4];"
        : "=r"(r[0]), "=r"(r[1]), "=r"(r[2]), "=r"(r[3]) : "r"(a));
}
__device__ __forceinline__ void mma16816(float* d, const uint32_t* a, const uint32_t* b) {
    asm volatile("mma.sync.aligned.m16n8k16.row.col.f32.f16.f16.f32 "
        "{%0,%1,%2,%3}, {%4,%5,%6,%7}, {%8,%9}, {%0,%1,%2,%3};"
        : "+f"(d[0]), "+f"(d[1]), "+f"(d[2]), "+f"(d[3])
        : "r"(a[0]), "r"(a[1]), "r"(a[2]), "r"(a[3]), "r"(b[0]), "r"(b[1]));
}
// pack two fp32 -> f16x2 (lo = zlo), then 2^x elementwise
__device__ __forceinline__ uint32_t exp2h2(float zhi, float zlo) {
    uint32_t u;
    asm("cvt.rn.f16x2.f32 %0, %1, %2;" : "=r"(u) : "f"(zhi), "f"(zlo));
    asm("ex2.approx.f16x2 %0, %0;" : "+r"(u));
    return u;
}
#define CP16(sa, ga) \
    asm volatile("cp.async.cg.shared.global [%0], [%1], 16;" :: "r"(sa), "l"(ga))
#define CP_COMMIT() asm volatile("cp.async.commit_group;" ::: "memory")
#define CP_WAIT2()  asm volatile("cp.async.wait_group 2;" ::: "memory")
#define CP_WAIT1()  asm volatile("cp.async.wait_group 1;" ::: "memory")
#define CP_WAIT0()  asm volatile("cp.async.wait_group 0;" ::: "memory")

// ---------------------------------------------------------------------------
// Merged elementwise kernel (R13, proven): PE-add + weight conversion.
// ---------------------------------------------------------------------------
#define PE_PAIRS  (BN*D_/2)
#define PE_BLOCKS (PE_PAIRS/256)
#define QKV_F4 (D_*QKVD/4)
#define LIN_F4 (D_*D_/4)
#define EW_BLOCKS (PE_BLOCKS + (QKV_F4 + LIN_F4)/256)

__global__ void elementwise_kernel(const float* __restrict__ x,
                                   const float* __restrict__ qkv_w,
                                   const float* __restrict__ lin_w) {
    if (blockIdx.x < PE_BLOCKS) {
        int i = blockIdx.x * blockDim.x + threadIdx.x;   // pair index
        int dp = i & (D_/2 - 1);
        int n = (i >> 8) & (N_ - 1);
        float inv = exp2f((float)dp * -0.051905126482615044f); // log2(1e4)/256
        float angle = (float)n * inv;
        float s, c;
        sincosf(angle, &s, &c);
        float2 xv = ((const float2*)x)[i];
        __half2 hv = __floats2half2_rn(xv.x + s, xv.y + c);
        ((__half2*)g_xh)[i] = hv;
    } else {
        int i = (blockIdx.x - PE_BLOCKS) * blockDim.x + threadIdx.x;
        const float* src;
        __half* dst;
        int j;
        if (i < QKV_F4) { src = qkv_w; dst = g_wqkv; j = i; }
        else            { src = lin_w; dst = g_wlin; j = i - QKV_F4; }
        float4 v = ((const float4*)src)[j];
        __half2 a = __floats2half2_rn(v.x, v.y);
        __half2 b = __floats2half2_rn(v.z, v.w);
        ((uint2*)dst)[j] = make_uint2(*(uint32_t*)&a, *(uint32_t*)&b);
    }
}

// ---------------------------------------------------------------------------
// HGEMM: block 128x128, 4 warps (2x2), warp tile 64x64, k-step 32, 2-stage
// cp.async. vs the 8-warp/64x32 version: MMAs per warp-iter 32->64, LDSM per
// warp-iter 12->16 (2x fragment reuse per smem byte), half the issue-slot
// pressure. Same accumulation order -> bit-identical results.
// ---------------------------------------------------------------------------
#define SA_ST 5120   // halves per A stage (128*40)
#define SB_ST 4352   // halves per B stage (32*136)

__device__ __forceinline__ void hg_issue(
    uint32_t sAa, uint32_t sBa, int stage,
    const __half* __restrict__ A, const __half* __restrict__ Bw,
    int m0, int n0, int k0, int N, int K, int tid)
{
    uint32_t sa = sAa + (uint32_t)stage * SA_ST * 2;
    uint32_t sb = sBa + (uint32_t)stage * SB_ST * 2;
    const int ar = tid >> 2, ac = (tid & 3) * 8;    // A: 32 rows per it
    const int br = tid >> 4, bc = (tid & 15) * 8;   // B: 8 rows per it
    #pragma unroll
    for (int it = 0; it < 4; it++) {
        CP16(sa + ((ar + it*32)*40 + ac)*2,
             A + (size_t)(m0 + ar + it*32)*K + k0 + ac);
        CP16(sb + ((br + it*8)*136 + bc)*2,
             Bw + (size_t)(k0 + br + it*8)*N + n0 + bc);
    }
}

template<int OUT_MODE>
__global__ __launch_bounds__(128) void hgemm_kernel(
    const __half* __restrict__ A, const __half* __restrict__ Bw,
    const float* __restrict__ bias, void* __restrict__ Cout,
    int M, int N, int K)
{
    __shared__ __half sA[2*SA_ST];
    __shared__ __half sB[2*SB_ST];

    const int tid = threadIdx.x;
    const int lane = tid & 31, warp = tid >> 5;
    const int wm = warp >> 1, wn = warp & 1;
    const int m0 = blockIdx.y * 128, n0 = blockIdx.x * 128;
    const int lq = lane >> 3;

    float acc[4][8][4];
    #pragma unroll
    for (int i = 0; i < 4; i++)
        #pragma unroll
        for (int j = 0; j < 8; j++)
            #pragma unroll
            for (int v = 0; v < 4; v++) acc[i][j][v] = 0.f;

    const uint32_t sAa = smem_u32(sA), sBa = smem_u32(sB);
    const int NK = K / 32;

    hg_issue(sAa, sBa, 0, A, Bw, m0, n0, 0, N, K, tid);  CP_COMMIT();
    hg_issue(sAa, sBa, 1, A, Bw, m0, n0, 32, N, K, tid); CP_COMMIT();

    for (int i = 0; i < NK; i++) {
        if (i == NK - 1) { CP_WAIT0(); } else { CP_WAIT1(); }
        __syncthreads();
        const uint32_t sa = sAa + (uint32_t)(i & 1) * SA_ST * 2;
        const uint32_t sb = sBa + (uint32_t)(i & 1) * SB_ST * 2;
        #pragma unroll
        for (int ks = 0; ks < 2; ks++) {
            uint32_t af[4][4];
            #pragma unroll
            for (int r = 0; r < 4; r++) {
                uint32_t addr = sa + (uint32_t)(((wm*64 + 16*r + (lane & 15))*40
                                  + ks*16 + (lane >> 4)*8) * 2);
                ldsm4(af[r], addr);
            }
            #pragma unroll
            for (int np = 0; np < 4; np++) {
                uint32_t bf[4];
                uint32_t addr = sb + (uint32_t)(((ks*16 + (lq & 1)*8 + (lane & 7))*136
                                  + wn*64 + np*16 + (lq >> 1)*8) * 2);
                ldsm4t(bf, addr);
                #pragma unroll
                for (int r = 0; r < 4; r++) {
                    mma16816(acc[r][2*np],   af[r], bf);
                    mma16816(acc[r][2*np+1], af[r], bf + 2);
                }
            }
        }
        __syncthreads();
        if (i + 2 < NK) {
            hg_issue(sAa, sBa, i & 1, A, Bw, m0, n0, (i+2)*32, N, K, tid);
            CP_COMMIT();
        }
    }

    const int g = lane >> 2, t = lane & 3;
    #pragma unroll
    for (int i = 0; i < 4; i++) {
        int r0 = m0 + wm*64 + 16*i + g;
        #pragma unroll
        for (int j = 0; j < 8; j++) {
            int col = n0 + wn*64 + 8*j + 2*t;
            if (OUT_MODE == 0) {
                __half* C = (__half*)Cout;
                __half2 h0 = __floats2half2_rn(acc[i][j][0], acc[i][j][1]);
                __half2 h1 = __floats2half2_rn(acc[i][j][2], acc[i][j][3]);
                *(__half2*)&C[(size_t)r0*N + col]     = h0;
                *(__half2*)&C[(size_t)(r0+8)*N + col] = h1;
            } else {
                float* C = (float*)Cout;
                float b0 = bias[col], b1 = bias[col+1];
                *(float2*)&C[(size_t)r0*N + col]     = make_float2(acc[i][j][0]+b0, acc[i][j][1]+b1);
                *(float2*)&C[(size_t)(r0+8)*N + col] = make_float2(acc[i][j][2]+b0, acc[i][j][3]+b1);
            }
        }
    }
}

// ---------------------------------------------------------------------------
// FA2 attention (R13 exact — best measured at 184us): 3-stage K/V ring,
// one barrier per kt, m32 warp tile, lm-via-MMA, packed f16x2 exp,
// interleaved PV(hf0)/QK(hf1).
// smem: 3 stages x (K[128][72] + V[128][72]) = 110.6 KB -> occupancy 2.
// ---------------------------------------------------------------------------
#define STG_B  36864u          // bytes per stage (K + V)
#define KV_B   18432u          // bytes per K (or V) tile
#define QOFF_H (2*18432)       // Q staging area: stage2 K-area, half index
#define ATTN_SMEM (3*36864)

__device__ __forceinline__ void issue_kv(uint32_t sma, int stage, int kt,
                                         int b, int h, int tid) {
    const __half* gk = g_qkvh + (size_t)(b*N_ + kt*128)*QKVD + h*HD_ + D_;
    uint32_t kb = sma + (uint32_t)stage * STG_B;
    uint32_t vb = kb + KV_B;
    #pragma unroll
    for (int it = 0; it < 8; it++) {
        int idx = tid + it*128;
        int r = idx >> 3, c = (idx & 7)*8;
        const __half* gp = gk + (size_t)r*QKVD + c;
        uint32_t so = (uint32_t)(r*72 + c)*2;
        CP16(kb + so, gp);
        CP16(vb + so, gp + D_);
    }
}

// QK for one hf (64 keys), both mt: K fragment shared across mt.
__device__ __forceinline__ void qk_hf(
    const uint32_t qf[2][4][4], uint32_t kb, int key0, int lq, int lane,
    float s[2][8][4])
{
    #pragma unroll
    for (int mt = 0; mt < 2; mt++)
        #pragma unroll
        for (int j = 0; j < 8; j++)
            #pragma unroll
            for (int v = 0; v < 4; v++) s[mt][j][v] = 0.f;
    #pragma unroll
    for (int ds = 0; ds < 4; ds++) {
        #pragma unroll
        for (int jp = 0; jp < 4; jp++) {
            uint32_t bf[4];
            uint32_t addr = kb + (uint32_t)((
                  (key0 + jp*16 + (lq >> 1)*8 + (lane & 7))*72
                + ds*16 + (lq & 1)*8) * 2);
            ldsm4(bf, addr);
            #pragma unroll
            for (int mt = 0; mt < 2; mt++) {
                mma16816(s[mt][2*jp],   qf[mt][ds], bf);
                mma16816(s[mt][2*jp+1], qf[mt][ds], bf + 2);
            }
        }
    }
}

// softmax for one hf: s -> pf (packed f16), both mt.
__device__ __forceinline__ void softmax_hf(
    const float s[2][8][4], uint32_t pf[2][4][4])
{
    const float EA = 0.125f * 1.4426950408889634f;
    const float EB = -8.f   * 1.4426950408889634f;
    #pragma unroll
    for (int mt = 0; mt < 2; mt++) {
        #pragma unroll
        for (int j = 0; j < 8; j++) {
            float z0 = fmaf(s[mt][j][0], EA, EB);
            float z1 = fmaf(s[mt][j][1], EA, EB);
            float z2 = fmaf(s[mt][j][2], EA, EB);
            float z3 = fmaf(s[mt][j][3], EA, EB);
            pf[mt][j >> 1][(j & 1)*2]     = exp2h2(z1, z0);
            pf[mt][j >> 1][(j & 1)*2 + 1] = exp2h2(z3, z2);
        }
    }
}

// PV + lm for one hf: V fragment shared across mt.
__device__ __forceinline__ void pv_hf(
    const uint32_t pf[2][4][4], uint32_t vb, int key0, int lq, int lane,
    float o[2][8][4], float lm[2][4], const uint32_t* onesb)
{
    #pragma unroll
    for (int jp = 0; jp < 4; jp++) {
        mma16816(lm[0], pf[0][jp], onesb);
        mma16816(lm[1], pf[1][jp], onesb);
    }
    #pragma unroll
    for (int jp = 0; jp < 4; jp++) {
        #pragma unroll
        for (int nn = 0; nn < 4; nn++) {
            uint32_t vf[4];
            uint32_t addr = vb + (uint32_t)((
                  (key0 + jp*16 + (lq & 1)*8 + (lane & 7))*72
                + nn*16 + (lq >> 1)*8) * 2);
            ldsm4t(vf, addr);
            #pragma unroll
            for (int mt = 0; mt < 2; mt++) {
                mma16816(o[mt][2*nn],   pf[mt][jp], vf);
                mma16816(o[mt][2*nn+1], pf[mt][jp], vf + 2);
            }
        }
    }
}

__global__ __launch_bounds__(128, 2) void attn_kernel() {
    extern __shared__ __half sm[];
    const uint32_t sma = smem_u32(sm);
    const int tid = threadIdx.x, lane = tid & 31, warp = tid >> 5;
    const int b = blockIdx.y >> 3, h = blockIdx.y & 7;
    const int q0 = blockIdx.x * 128;
    const int lq = lane >> 3;

    // prefetch K/V for kt=0,1 into stages 0,1 (don't touch stage 2 yet)
    issue_kv(sma, 0, 0, b, h, tid); CP_COMMIT();
    issue_kv(sma, 1, 1, b, h, tid); CP_COMMIT();

    // Q tile staged through stage-2's K-area (raw fp16; softmax folds scale)
    #pragma unroll
    for (int it = 0; it < 8; it++) {
        int idx = tid + it * 128;
        int r = idx >> 3, c = (idx & 7) * 8;
        *(uint4*)&sm[QOFF_H + r*72 + c] =
            *(const uint4*)&g_qkvh[(size_t)(b*N_ + q0 + r)*QKVD + h*HD_ + c];
    }
    __syncthreads();

    // Q fragments: warp rows [warp*32, warp*32+32), mt halves
    uint32_t qf[2][4][4];
    #pragma unroll
    for (int mt = 0; mt < 2; mt++)
        #pragma unroll
        for (int ds = 0; ds < 4; ds++) {
            uint32_t addr = sma + (uint32_t)((QOFF_H
                              + (warp*32 + mt*16 + (lane & 15))*72
                              + ds*16 + (lane >> 4)*8) * 2);
            ldsm4(qf[mt][ds], addr);
        }

    float o[2][8][4];
    #pragma unroll
    for (int mt = 0; mt < 2; mt++)
        #pragma unroll
        for (int j = 0; j < 8; j++)
            #pragma unroll
            for (int v = 0; v < 4; v++) o[mt][j][v] = 0.f;
    float lm[2][4] = {{0.f,0.f,0.f,0.f},{0.f,0.f,0.f,0.f}};
    uint32_t onesb[2] = {0x3C003C00u, 0x3C003C00u};  // f16 1.0 x4

    int cur = 0;   // stage holding kt's K/V
    for (int kt = 0; kt < 32; kt++) {
        __syncthreads();
        if (kt + 2 < 32) {
            int pre = cur + 2; if (pre >= 3) pre -= 3;
            issue_kv(sma, pre, kt + 2, b, h, tid);
            CP_COMMIT();
            CP_WAIT2();
        } else if (kt == 30) {
            CP_WAIT1();
        } else {
            CP_WAIT0();
        }
        const uint32_t kb = sma + (uint32_t)cur * STG_B;
        const uint32_t vb = kb + KV_B;

        float s[2][8][4];
        uint32_t pf[2][4][4];

        // hf0: S, softmax
        qk_hf(qf, kb, 0, lq, lane, s);
        softmax_hf(s, pf);
        // interleave: QK(hf1) into s (freed) + PV(hf0) from pf — independent
        {
            // lm(hf0)
            #pragma unroll
            for (int jp = 0; jp < 4; jp++) {
                mma16816(lm[0], pf[0][jp], onesb);
                mma16816(lm[1], pf[1][jp], onesb);
            }
            // zero s for hf1
            #pragma unroll
            for (int mt = 0; mt < 2; mt++)
                #pragma unroll
                for (int j = 0; j < 8; j++)
                    #pragma unroll
                    for (int v = 0; v < 4; v++) s[mt][j][v] = 0.f;
            // fused loop: step drives both QK(hf1) ds-slice and PV(hf0) jp-slice
            #pragma unroll
            for (int st = 0; st < 4; st++) {
                // QK(hf1), ds = st
                #pragma unroll
                for (int jp = 0; jp < 4; jp++) {
                    uint32_t bf[4];
                    uint32_t addr = kb + (uint32_t)((
                          (64 + jp*16 + (lq >> 1)*8 + (lane & 7))*72
                        + st*16 + (lq & 1)*8) * 2);
                    ldsm4(bf, addr);
                    mma16816(s[0][2*jp],   qf[0][st], bf);
                    mma16816(s[0][2*jp+1], qf[0][st], bf + 2);
                    mma16816(s[1][2*jp],   qf[1][st], bf);
                    mma16816(s[1][2*jp+1], qf[1][st], bf + 2);
                }
                // PV(hf0), jp = st
                #pragma unroll
                for (int nn = 0; nn < 4; nn++) {
                    uint32_t vf[4];
                    uint32_t addr = vb + (uint32_t)((
                          (st*16 + (lq & 1)*8 + (lane & 7))*72
                        + nn*16 + (lq >> 1)*8) * 2);
                    ldsm4t(vf, addr);
                    mma16816(o[0][2*nn],   pf[0][st], vf);
                    mma16816(o[0][2*nn+1], pf[0][st], vf + 2);
                    mma16816(o[1][2*nn],   pf[1][st], vf);
                    mma16816(o[1][2*nn+1], pf[1][st], vf + 2);
                }
            }
        }
        // hf1: softmax, lm, PV
        softmax_hf(s, pf);
        pv_hf(pf, vb, 64, lq, lane, o, lm, onesb);

        if (++cur == 3) cur = 0;
    }

    const int g = lane >> 2, t = lane & 3;
    #pragma unroll
    for (int mt = 0; mt < 2; mt++) {
        float inv0 = 1.f / lm[mt][0], inv1 = 1.f / lm[mt][2];
        const int r0 = q0 + warp*32 + mt*16 + g;
        #pragma unroll
        for (int j = 0; j < 8; j++) {
            int col = h*HD_ + 8*j + 2*t;
            __half2 h0 = __floats2half2_rn(o[mt][j][0]*inv0, o[mt][j][1]*inv0);
            __half2 h1 = __floats2half2_rn(o[mt][j][2]*inv1, o[mt][j][3]*inv1);
            *(__half2*)&g_aoh[(size_t)(b*N_ + r0)*D_ + col]     = h0;
            *(__half2*)&g_aoh[(size_t)(b*N_ + r0 + 8)*D_ + col] = h1;
        }
    }
}

// ---------------------------------------------------------------------------
extern "C" void kernel_launch(void* const* d_in, const int* in_sizes, int n_in,
                              void* d_out, int out_size) {
    const float* x     = (const float*)d_in[0];
    const float* qkv_w = (const float*)d_in[1];
    const float* lin_w = (const float*)d_in[2];
    const float* lin_b = (const float*)d_in[3];
    float* out = (float*)d_out;

    __half *xh, *wqkv, *wlin, *qkvh, *aoh;
    cudaGetSymbolAddress((void**)&xh,   g_xh);
    cudaGetSymbolAddress((void**)&wqkv, g_wqkv);
    cudaGetSymbolAddress((void**)&wlin, g_wlin);
    cudaGetSymbolAddress((void**)&qkvh, g_qkvh);
    cudaGetSymbolAddress((void**)&aoh,  g_aoh);

    cudaFuncSetAttribute(attn_kernel,
                         cudaFuncAttributeMaxDynamicSharedMemorySize, ATTN_SMEM);

    elementwise_kernel<<<EW_BLOCKS, 256>>>(x, qkv_w, lin_w);

    hgemm_kernel<0><<<dim3(QKVD/128, BN/128), 128>>>(
        xh, wqkv, nullptr, qkvh, BN, QKVD, D_);

    attn_kernel<<<dim3(N_/128, B_*H_), 128, ATTN_SMEM>>>();

    hgemm_kernel<1><<<dim3(D_/128, BN/128), 128>>>(
        aoh, wlin, lin_b, out, BN, D_, D_);
}